// round 1
// baseline (speedup 1.0000x reference)
#include <cuda_runtime.h>
#include <cuda_bf16.h>

#define NN 100000
#define NE 1200000
#define NG 2048
#define DD 64

// Scratch (allocation-free, __device__ globals)
__device__ float g_h0[(size_t)NN * DD];
__device__ float g_h1[(size_t)NN * DD];
__device__ float g_h2[(size_t)NN * DD];
__device__ float g_agg[(size_t)NN * DD];
__device__ float g_cnt[NN];
__device__ float g_pool[(size_t)NG * DD];
__device__ float g_gcnt[NG];

// h0[n] = emb[x[n]]  (float4 granularity, 16 threads/node)
__global__ void k_gather(const int* __restrict__ x, const float* __restrict__ emb,
                         float* __restrict__ h) {
    int t = blockIdx.x * blockDim.x + threadIdx.x;
    if (t >= NN * 16) return;
    int n = t >> 4, j = t & 15;
    const float4* e = (const float4*)(emb + (size_t)x[n] * DD);
    ((float4*)(h + (size_t)n * DD))[j] = e[j];
}

// cnt[dst[e]] += 1
__global__ void k_degree(const int* __restrict__ dst, float* __restrict__ cnt) {
    int e = blockIdx.x * blockDim.x + threadIdx.x;
    if (e < NE) atomicAdd(&cnt[dst[e]], 1.0f);
}

// agg[dst[e]] += h[src[e]]   (16 threads/edge, float4 loads, 4 atomics each)
__global__ void k_scatter(const int* __restrict__ src, const int* __restrict__ dst,
                          const float* __restrict__ h, float* __restrict__ agg) {
    int t = blockIdx.x * blockDim.x + threadIdx.x;
    if (t >= NE * 16) return;
    int e = t >> 4, j = t & 15;
    int s = src[e], d = dst[e];
    float4 v = ((const float4*)(h + (size_t)s * DD))[j];
    float* a = agg + (size_t)d * DD + (size_t)j * 4;
    atomicAdd(a + 0, v.x);
    atomicAdd(a + 1, v.y);
    atomicAdd(a + 2, v.z);
    atomicAdd(a + 3, v.w);
}

// out[n] = relu( (agg[n]/max(cnt,1)) @ Wl^T + bl + h[n] @ Wr^T )
// Block: 256 threads = 4 nodes x 64 output dims. Weights cached transposed in smem.
__global__ __launch_bounds__(256) void k_linear(
    const float* __restrict__ agg, const float* __restrict__ cnt,
    const float* __restrict__ h,
    const float* __restrict__ Wl, const float* __restrict__ bl,
    const float* __restrict__ Wr, float* out)
{
    __shared__ float sWl[DD * DD];   // transposed: sWl[k*64+d] = Wl[d*64+k]
    __shared__ float sWr[DD * DD];
    __shared__ float sa[4][DD];
    __shared__ float sh[4][DD];

    int tid = threadIdx.x;
    for (int i = tid; i < DD * DD; i += 256) {
        int dd = i >> 6, k = i & 63;
        sWl[k * DD + dd] = Wl[i];
        sWr[k * DD + dd] = Wr[i];
    }
    __syncthreads();

    int local = tid >> 6;      // 0..3
    int d = tid & 63;          // output dim
    float bias = bl[d];

    for (int n0 = blockIdx.x * 4; n0 < NN; n0 += gridDim.x * 4) {
        int n = n0 + local;
        if (n < NN) {
            float inv = 1.0f / fmaxf(cnt[n], 1.0f);
            sa[local][d] = agg[(size_t)n * DD + d] * inv;
            sh[local][d] = h[(size_t)n * DD + d];
        }
        __syncthreads();
        if (n < NN) {
            float acc = bias;
            #pragma unroll
            for (int k = 0; k < DD; k++) {
                acc += sa[local][k] * sWl[k * DD + d];
                acc += sh[local][k] * sWr[k * DD + d];
            }
            out[(size_t)n * DD + d] = fmaxf(acc, 0.0f);
        }
        __syncthreads();
    }
}

// pooled[batch[n]] += h[n]; gcnt[batch[n]] += 1
__global__ void k_pool(const float* __restrict__ h, const int* __restrict__ batch,
                       float* __restrict__ pool, float* __restrict__ gcnt) {
    int t = blockIdx.x * blockDim.x + threadIdx.x;
    if (t >= NN * 16) return;
    int n = t >> 4, j = t & 15;
    int g = batch[n];
    float4 v = ((const float4*)(h + (size_t)n * DD))[j];
    float* p = pool + (size_t)g * DD + (size_t)j * 4;
    atomicAdd(p + 0, v.x);
    atomicAdd(p + 1, v.y);
    atomicAdd(p + 2, v.z);
    atomicAdd(p + 3, v.w);
    if (j == 0) atomicAdd(&gcnt[g], 1.0f);
}

// out[g,c] = (pool[g]/gcnt[g]) . Wout[c] + bout[c]
__global__ void k_out(const float* __restrict__ pool, const float* __restrict__ gcnt,
                      const float* __restrict__ Wout, const float* __restrict__ bout,
                      float* __restrict__ out) {
    int t = blockIdx.x * blockDim.x + threadIdx.x;
    if (t >= NG * 2) return;
    int g = t >> 1, c = t & 1;
    float inv = 1.0f / fmaxf(gcnt[g], 1.0f);
    float acc = bout[c];
    const float* p = pool + (size_t)g * DD;
    const float* w = Wout + (size_t)c * DD;
    #pragma unroll
    for (int k = 0; k < DD; k++) acc += p[k] * inv * w[k];
    out[(size_t)g * 2 + c] = acc;
}

extern "C" void kernel_launch(void* const* d_in, const int* in_sizes, int n_in,
                              void* d_out, int out_size) {
    const int*   x     = (const int*)d_in[0];
    const int*   ei    = (const int*)d_in[1];
    const int*   src   = ei;          // edge_index[0]
    const int*   dst   = ei + NE;     // edge_index[1]
    const int*   batch = (const int*)d_in[2];
    const float* emb   = (const float*)d_in[3];
    const float* W1l   = (const float*)d_in[4];
    const float* b1l   = (const float*)d_in[5];
    const float* W1r   = (const float*)d_in[6];
    const float* W2l   = (const float*)d_in[7];
    const float* b2l   = (const float*)d_in[8];
    const float* W2r   = (const float*)d_in[9];
    const float* Wout  = (const float*)d_in[10];
    const float* bout  = (const float*)d_in[11];
    float* out = (float*)d_out;

    float *h0, *h1, *h2, *agg, *cnt, *pool, *gcnt;
    cudaGetSymbolAddress((void**)&h0,   g_h0);
    cudaGetSymbolAddress((void**)&h1,   g_h1);
    cudaGetSymbolAddress((void**)&h2,   g_h2);
    cudaGetSymbolAddress((void**)&agg,  g_agg);
    cudaGetSymbolAddress((void**)&cnt,  g_cnt);
    cudaGetSymbolAddress((void**)&pool, g_pool);
    cudaGetSymbolAddress((void**)&gcnt, g_gcnt);

    cudaMemsetAsync(cnt,  0, (size_t)NN * sizeof(float));
    cudaMemsetAsync(agg,  0, (size_t)NN * DD * sizeof(float));
    cudaMemsetAsync(pool, 0, (size_t)NG * DD * sizeof(float));
    cudaMemsetAsync(gcnt, 0, (size_t)NG * sizeof(float));

    const int T = 256;
    k_gather<<<(NN * 16 + T - 1) / T, T>>>(x, emb, h0);
    k_degree<<<(NE + T - 1) / T, T>>>(dst, cnt);

    // Layer 1
    k_scatter<<<(NE * 16 + T - 1) / T, T>>>(src, dst, h0, agg);
    k_linear<<<888, 256>>>(agg, cnt, h0, W1l, b1l, W1r, h1);

    // Layer 2
    cudaMemsetAsync(agg, 0, (size_t)NN * DD * sizeof(float));
    k_scatter<<<(NE * 16 + T - 1) / T, T>>>(src, dst, h1, agg);
    k_linear<<<888, 256>>>(agg, cnt, h1, W2l, b2l, W2r, h2);

    // Pool + classify
    k_pool<<<(NN * 16 + T - 1) / T, T>>>(h2, batch, pool, gcnt);
    k_out<<<(NG * 2 + 127) / 128, 128>>>(pool, gcnt, Wout, bout, out);
}

// round 3
// speedup vs baseline: 1.8813x; 1.8813x over previous
#include <cuda_runtime.h>
#include <cuda_bf16.h>

#define NN 100000
#define NE 1200000
#define NG 2048
#define DD 64

// Scratch (allocation-free, __device__ globals)
__device__ float g_h0[(size_t)NN * DD];
__device__ float g_h1[(size_t)NN * DD];
__device__ float g_h2[(size_t)NN * DD];
__device__ float g_agg[(size_t)NN * DD];
__device__ float g_cnt[NN];
__device__ float g_pool[(size_t)NG * DD];
__device__ float g_gcnt[NG];

// h0[n] = emb[x[n]]
__global__ void k_gather(const int* __restrict__ x, const float* __restrict__ emb,
                         float* __restrict__ h) {
    int t = blockIdx.x * blockDim.x + threadIdx.x;
    if (t >= NN * 16) return;
    int n = t >> 4, j = t & 15;
    const float4* e = (const float4*)(emb + (size_t)x[n] * DD);
    ((float4*)(h + (size_t)n * DD))[j] = e[j];
}

// cnt[dst[e]] += 1
__global__ void k_degree(const int* __restrict__ dst, float* __restrict__ cnt) {
    int e = blockIdx.x * blockDim.x + threadIdx.x;
    if (e < NE) atomicAdd(&cnt[dst[e]], 1.0f);
}

__device__ __forceinline__ void red_v4(float* p, float4 v) {
    asm volatile("red.global.add.v4.f32 [%0], {%1, %2, %3, %4};"
                 :: "l"(p), "f"(v.x), "f"(v.y), "f"(v.z), "f"(v.w) : "memory");
}

// agg[dst[e]] += h[src[e]]
// 4 threads/edge; each thread covers 16 consecutive floats (4x red.v4).
__global__ void k_scatter(const int* __restrict__ src, const int* __restrict__ dst,
                          const float* __restrict__ h, float* __restrict__ agg) {
    int t = blockIdx.x * blockDim.x + threadIdx.x;
    if (t >= NE * 4) return;
    int e = t >> 2, j = t & 3;
    int s = src[e], d = dst[e];
    const float4* hr = (const float4*)(h + (size_t)s * DD) + j * 4;
    float* a = agg + (size_t)d * DD + (size_t)j * 16;
    #pragma unroll
    for (int i = 0; i < 4; i++) {
        float4 v = hr[i];
        red_v4(a + i * 4, v);
    }
}

// out[n] = relu( (agg[n]/max(cnt,1)) @ Wl^T + bl + h[n] @ Wr^T )
// GEMM tiling: 64 nodes x 64 dims per block, 256 threads, 4x4 micro-tile.
// smem: sW[128][64] (Wl^T ; Wr^T), sA[128][65] (aggT scaled ; hT), dynamic 66048B.
__global__ __launch_bounds__(256) void k_linear(
    const float* __restrict__ agg, const float* __restrict__ cnt,
    const float* __restrict__ h,
    const float* __restrict__ Wl, const float* __restrict__ bl,
    const float* __restrict__ Wr, float* __restrict__ out)
{
    extern __shared__ float smem[];
    float* sW = smem;               // [128][64]
    float* sA = smem + 128 * 64;    // [128][65]
    const int tid = threadIdx.x;

    // Load weights transposed once: sW[k][d] = Wl[d][k]; sW[64+k][d] = Wr[d][k]
    for (int i = tid; i < 64 * 64; i += 256) {
        int d = i >> 6, k = i & 63;
        float wl = Wl[i], wr = Wr[i];
        sW[k * 64 + d]        = wl;
        sW[(64 + k) * 64 + d] = wr;
    }

    const int q  = tid & 15;     // node quad index
    const int dq = tid >> 4;     // dim quad index
    const int m0 = q * 4;
    const int d0 = dq * 4;
    float4 bias = *(const float4*)&bl[d0];
    __syncthreads();

    for (int n0 = blockIdx.x * 64; n0 < NN; n0 += gridDim.x * 64) {
        // Stage A tile transposed: rows 0..63 = agg^T (scaled by 1/cnt), 64..127 = h^T
        for (int i = tid; i < 64 * 16; i += 256) {
            int m = i >> 4;           // node within tile
            int kq = i & 15;          // k-quad
            int n = n0 + m;
            float4 va = make_float4(0.f, 0.f, 0.f, 0.f);
            float4 vh = va;
            float inv = 1.0f;
            if (n < NN) {
                inv = 1.0f / fmaxf(cnt[n], 1.0f);
                va = ((const float4*)(agg + (size_t)n * DD))[kq];
                vh = ((const float4*)(h   + (size_t)n * DD))[kq];
            }
            int k = kq * 4;
            sA[(k + 0) * 65 + m] = va.x * inv;
            sA[(k + 1) * 65 + m] = va.y * inv;
            sA[(k + 2) * 65 + m] = va.z * inv;
            sA[(k + 3) * 65 + m] = va.w * inv;
            sA[(64 + k + 0) * 65 + m] = vh.x;
            sA[(64 + k + 1) * 65 + m] = vh.y;
            sA[(64 + k + 2) * 65 + m] = vh.z;
            sA[(64 + k + 3) * 65 + m] = vh.w;
        }
        __syncthreads();

        float acc[4][4];
        #pragma unroll
        for (int i = 0; i < 4; i++) {
            acc[i][0] = bias.x; acc[i][1] = bias.y;
            acc[i][2] = bias.z; acc[i][3] = bias.w;
        }

        #pragma unroll 4
        for (int k = 0; k < 128; k++) {
            float4 w = *(const float4*)&sW[k * 64 + d0];
            #pragma unroll
            for (int i = 0; i < 4; i++) {
                float a = sA[k * 65 + m0 + i];
                acc[i][0] += a * w.x;
                acc[i][1] += a * w.y;
                acc[i][2] += a * w.z;
                acc[i][3] += a * w.w;
            }
        }

        #pragma unroll
        for (int i = 0; i < 4; i++) {
            int n = n0 + m0 + i;
            if (n < NN) {
                float4 o = make_float4(fmaxf(acc[i][0], 0.f), fmaxf(acc[i][1], 0.f),
                                       fmaxf(acc[i][2], 0.f), fmaxf(acc[i][3], 0.f));
                *(float4*)&out[(size_t)n * DD + d0] = o;
            }
        }
        __syncthreads();
    }
}

// pooled[batch[n]] += h[n]; gcnt[batch[n]] += 1
// 4 threads/node; each thread covers 16 consecutive floats (4x red.v4).
__global__ void k_pool(const float* __restrict__ h, const int* __restrict__ batch,
                       float* __restrict__ pool, float* __restrict__ gcnt) {
    int t = blockIdx.x * blockDim.x + threadIdx.x;
    if (t >= NN * 4) return;
    int n = t >> 2, j = t & 3;
    int g = batch[n];
    const float4* hr = (const float4*)(h + (size_t)n * DD) + j * 4;
    float* p = pool + (size_t)g * DD + (size_t)j * 16;
    #pragma unroll
    for (int i = 0; i < 4; i++) {
        float4 v = hr[i];
        red_v4(p + i * 4, v);
    }
    if (j == 0) atomicAdd(&gcnt[g], 1.0f);
}

// out[g,c] = (pool[g]/gcnt[g]) . Wout[c] + bout[c]
__global__ void k_out(const float* __restrict__ pool, const float* __restrict__ gcnt,
                      const float* __restrict__ Wout, const float* __restrict__ bout,
                      float* __restrict__ out) {
    int t = blockIdx.x * blockDim.x + threadIdx.x;
    if (t >= NG * 2) return;
    int g = t >> 1, c = t & 1;
    float inv = 1.0f / fmaxf(gcnt[g], 1.0f);
    float acc = bout[c];
    const float* p = pool + (size_t)g * DD;
    const float* w = Wout + (size_t)c * DD;
    #pragma unroll
    for (int k = 0; k < DD; k++) acc += p[k] * inv * w[k];
    out[(size_t)g * 2 + c] = acc;
}

extern "C" void kernel_launch(void* const* d_in, const int* in_sizes, int n_in,
                              void* d_out, int out_size) {
    const int*   x     = (const int*)d_in[0];
    const int*   ei    = (const int*)d_in[1];
    const int*   src   = ei;          // edge_index[0]
    const int*   dst   = ei + NE;     // edge_index[1]
    const int*   batch = (const int*)d_in[2];
    const float* emb   = (const float*)d_in[3];
    const float* W1l   = (const float*)d_in[4];
    const float* b1l   = (const float*)d_in[5];
    const float* W1r   = (const float*)d_in[6];
    const float* W2l   = (const float*)d_in[7];
    const float* b2l   = (const float*)d_in[8];
    const float* W2r   = (const float*)d_in[9];
    const float* Wout  = (const float*)d_in[10];
    const float* bout  = (const float*)d_in[11];
    float* out = (float*)d_out;

    float *h0, *h1, *h2, *agg, *cnt, *pool, *gcnt;
    cudaGetSymbolAddress((void**)&h0,   g_h0);
    cudaGetSymbolAddress((void**)&h1,   g_h1);
    cudaGetSymbolAddress((void**)&h2,   g_h2);
    cudaGetSymbolAddress((void**)&agg,  g_agg);
    cudaGetSymbolAddress((void**)&cnt,  g_cnt);
    cudaGetSymbolAddress((void**)&pool, g_pool);
    cudaGetSymbolAddress((void**)&gcnt, g_gcnt);

    const int SMEM_LIN = (128 * 64 + 128 * 65) * 4;   // 66048 bytes
    cudaFuncSetAttribute(k_linear, cudaFuncAttributeMaxDynamicSharedMemorySize, SMEM_LIN);

    cudaMemsetAsync(cnt,  0, (size_t)NN * sizeof(float));
    cudaMemsetAsync(agg,  0, (size_t)NN * DD * sizeof(float));
    cudaMemsetAsync(pool, 0, (size_t)NG * DD * sizeof(float));
    cudaMemsetAsync(gcnt, 0, (size_t)NG * sizeof(float));

    const int T = 256;
    k_gather<<<(NN * 16 + T - 1) / T, T>>>(x, emb, h0);
    k_degree<<<(NE + T - 1) / T, T>>>(dst, cnt);

    // Layer 1
    k_scatter<<<(NE * 4 + T - 1) / T, T>>>(src, dst, h0, agg);
    k_linear<<<444, 256, SMEM_LIN>>>(agg, cnt, h0, W1l, b1l, W1r, h1);

    // Layer 2
    cudaMemsetAsync(agg, 0, (size_t)NN * DD * sizeof(float));
    k_scatter<<<(NE * 4 + T - 1) / T, T>>>(src, dst, h1, agg);
    k_linear<<<444, 256, SMEM_LIN>>>(agg, cnt, h1, W2l, b2l, W2r, h2);

    // Pool + classify
    k_pool<<<(NN * 4 + T - 1) / T, T>>>(h2, batch, pool, gcnt);
    k_out<<<(NG * 2 + 127) / 128, 128>>>(pool, gcnt, Wout, bout, out);
}

// round 4
// speedup vs baseline: 2.8698x; 1.5254x over previous
#include <cuda_runtime.h>
#include <cuda_bf16.h>

#define NN 100000
#define NE 1200000
#define NG 2048
#define DD 64
#define SCAN_B 1024
#define SCAN_NB 98   // 98*1024 = 100352 >= NN

// Scratch (allocation-free, __device__ globals)
__device__ float g_h0[(size_t)NN * DD];
__device__ float g_h1[(size_t)NN * DD];
__device__ float g_h2[(size_t)NN * DD];
__device__ float g_agg[(size_t)NN * DD];      // mean buffer
__device__ float g_pool[(size_t)NG * DD];
__device__ float g_gcnt[NG];
__device__ int   g_deg[NN];
__device__ int   g_off[NN];
__device__ int   g_cursor[NN];
__device__ int   g_elist[NE];
__device__ int   g_bsum[SCAN_NB];
__device__ int   g_bpre[SCAN_NB];

// ---------- packed fp32 helpers ----------
__device__ __forceinline__ unsigned long long pk2(float lo, float hi) {
    unsigned long long r;
    asm("mov.b64 %0, {%1, %2};" : "=l"(r) : "f"(lo), "f"(hi));
    return r;
}
__device__ __forceinline__ void upk2(float& lo, float& hi, unsigned long long v) {
    asm("mov.b64 {%0, %1}, %2;" : "=f"(lo), "=f"(hi) : "l"(v));
}
__device__ __forceinline__ void ffma2(unsigned long long& acc, unsigned long long a,
                                      unsigned long long b) {
    asm("fma.rn.f32x2 %0, %1, %2, %0;" : "+l"(acc) : "l"(a), "l"(b));
}
__device__ __forceinline__ void red_v4(float* p, float4 v) {
    asm volatile("red.global.add.v4.f32 [%0], {%1, %2, %3, %4};"
                 :: "l"(p), "f"(v.x), "f"(v.y), "f"(v.z), "f"(v.w) : "memory");
}

// ---------- h0[n] = emb[x[n]] ----------
__global__ void k_gather(const int* __restrict__ x, const float* __restrict__ emb,
                         float* __restrict__ h) {
    int t = blockIdx.x * blockDim.x + threadIdx.x;
    if (t >= NN * 16) return;
    int n = t >> 4, j = t & 15;
    const float4* e = (const float4*)(emb + (size_t)x[n] * DD);
    ((float4*)(h + (size_t)n * DD))[j] = e[j];
}

// ---------- CSR build ----------
__global__ void k_deg(const int* __restrict__ dst, int* __restrict__ deg) {
    int e = blockIdx.x * blockDim.x + threadIdx.x;
    if (e < NE) atomicAdd(&deg[dst[e]], 1);
}

__global__ void k_scan_part(const int* __restrict__ deg, int* __restrict__ bsum) {
    __shared__ int s[SCAN_B];
    int t = threadIdx.x, n = blockIdx.x * SCAN_B + t;
    s[t] = (n < NN) ? deg[n] : 0;
    __syncthreads();
    for (int d = SCAN_B / 2; d > 0; d >>= 1) {
        if (t < d) s[t] += s[t + d];
        __syncthreads();
    }
    if (t == 0) bsum[blockIdx.x] = s[0];
}

__global__ void k_scan_mid(const int* __restrict__ bsum, int* __restrict__ bpre) {
    __shared__ int s[128];
    int t = threadIdx.x;
    int v = (t < SCAN_NB) ? bsum[t] : 0;
    s[t] = v;
    __syncthreads();
    for (int d = 1; d < 128; d <<= 1) {
        int x = (t >= d) ? s[t - d] : 0;
        __syncthreads();
        s[t] += x;
        __syncthreads();
    }
    if (t < SCAN_NB) bpre[t] = s[t] - v;   // exclusive
}

__global__ void k_scan_add(const int* __restrict__ deg, const int* __restrict__ bpre,
                           int* __restrict__ off) {
    __shared__ int s[SCAN_B];
    int t = threadIdx.x, n = blockIdx.x * SCAN_B + t;
    int v = (n < NN) ? deg[n] : 0;
    s[t] = v;
    __syncthreads();
    for (int d = 1; d < SCAN_B; d <<= 1) {
        int x = (t >= d) ? s[t - d] : 0;
        __syncthreads();
        s[t] += x;
        __syncthreads();
    }
    if (n < NN) off[n] = bpre[blockIdx.x] + s[t] - v;   // exclusive
}

__global__ void k_fill(const int* __restrict__ src, const int* __restrict__ dst,
                       const int* __restrict__ off, int* __restrict__ cursor,
                       int* __restrict__ elist) {
    int e = blockIdx.x * blockDim.x + threadIdx.x;
    if (e >= NE) return;
    int d = dst[e];
    int p = atomicAdd(&cursor[d], 1);
    elist[off[d] + p] = src[e];
}

// ---------- mean aggregation: one warp per node ----------
__global__ __launch_bounds__(256) void k_aggmean(
    const float* __restrict__ h, const int* __restrict__ elist,
    const int* __restrict__ off, const int* __restrict__ deg,
    float* __restrict__ mean) {
    int w = (blockIdx.x * blockDim.x + threadIdx.x) >> 5;
    int lane = threadIdx.x & 31;
    if (w >= NN) return;
    int beg = off[w], dg = deg[w];
    float2 a0 = make_float2(0.f, 0.f), a1 = a0;
    int i = beg, end = beg + dg;
    for (; i + 1 < end; i += 2) {
        int s0 = elist[i], s1 = elist[i + 1];
        float2 v0 = ((const float2*)(h + (size_t)s0 * DD))[lane];
        float2 v1 = ((const float2*)(h + (size_t)s1 * DD))[lane];
        a0.x += v0.x; a0.y += v0.y;
        a1.x += v1.x; a1.y += v1.y;
    }
    if (i < end) {
        int s0 = elist[i];
        float2 v0 = ((const float2*)(h + (size_t)s0 * DD))[lane];
        a0.x += v0.x; a0.y += v0.y;
    }
    float inv = 1.0f / (float)max(dg, 1);
    float2 o = make_float2((a0.x + a1.x) * inv, (a0.y + a1.y) * inv);
    ((float2*)(mean + (size_t)w * DD))[lane] = o;
}

// ---------- fused dual GEMM + bias + relu ----------
// out[n] = relu( mean[n] @ Wl^T + bl + h[n] @ Wr^T )
// 64 nodes x 64 dims per block, 256 threads, 4x4 micro-tile, FFMA2 (fma.rn.f32x2).
#define SA_STRIDE 68
__global__ __launch_bounds__(256) void k_linear(
    const float* __restrict__ mean, const float* __restrict__ h,
    const float* __restrict__ Wl, const float* __restrict__ bl,
    const float* __restrict__ Wr, float* __restrict__ out)
{
    extern __shared__ float smem[];
    float* sW = smem;                 // [128][64]
    float* sA = smem + 128 * 64;      // [128][SA_STRIDE] swizzled
    const int tid = threadIdx.x;

    // Weights transposed: sW[k][d] = Wl[d][k]; sW[64+k][d] = Wr[d][k]
    for (int i = tid; i < 64 * 64; i += 256) {
        int d = i >> 6, k = i & 63;
        sW[k * 64 + d]        = Wl[i];
        sW[(64 + k) * 64 + d] = Wr[i];
    }

    const int q  = tid & 15;     // node quad
    const int dq = tid >> 4;     // dim quad
    const int d0 = dq * 4;
    float4 bias = *(const float4*)&bl[d0];
    __syncthreads();

    const float4* m4 = (const float4*)mean;
    const float4* h4 = (const float4*)h;

    for (int n0 = blockIdx.x * 64; n0 < NN; n0 += gridDim.x * 64) {
        // Stage A^T swizzled: rows 0..63 = mean^T, 64..127 = h^T
        for (int i = tid; i < 64 * 16; i += 256) {
            int m = i >> 4, kq = i & 15;
            int n = n0 + m;
            float4 va = make_float4(0.f, 0.f, 0.f, 0.f), vh = va;
            if (n < NN) {
                va = m4[(size_t)n * 16 + kq];
                vh = h4[(size_t)n * 16 + kq];
            }
            int mb = m >> 2, mw = m & 3;
            int col = ((mb + kq) & 15) * 4 + mw;
            int k = kq * 4;
            sA[(k + 0) * SA_STRIDE + col] = va.x;
            sA[(k + 1) * SA_STRIDE + col] = va.y;
            sA[(k + 2) * SA_STRIDE + col] = va.z;
            sA[(k + 3) * SA_STRIDE + col] = va.w;
            sA[(64 + k + 0) * SA_STRIDE + col] = vh.x;
            sA[(64 + k + 1) * SA_STRIDE + col] = vh.y;
            sA[(64 + k + 2) * SA_STRIDE + col] = vh.z;
            sA[(64 + k + 3) * SA_STRIDE + col] = vh.w;
        }
        __syncthreads();

        // acc[node i][dim-pair j] : f32x2 over dims (d0+2j, d0+2j+1)
        unsigned long long acc[4][2];
        unsigned long long b01 = pk2(bias.x, bias.y);
        unsigned long long b23 = pk2(bias.z, bias.w);
        #pragma unroll
        for (int i = 0; i < 4; i++) { acc[i][0] = b01; acc[i][1] = b23; }

        #pragma unroll
        for (int kq = 0; kq < 32; kq++) {
            int col = ((q + kq) & 15) * 4;
            const float* ar = &sA[(kq * 4) * SA_STRIDE + col];
            #pragma unroll
            for (int c = 0; c < 4; c++) {
                int k = kq * 4 + c;
                float4 a = *(const float4*)(ar + c * SA_STRIDE);
                float4 w = *(const float4*)&sW[k * 64 + d0];
                unsigned long long w01 = pk2(w.x, w.y);
                unsigned long long w23 = pk2(w.z, w.w);
                unsigned long long ax = pk2(a.x, a.x);
                unsigned long long ay = pk2(a.y, a.y);
                unsigned long long az = pk2(a.z, a.z);
                unsigned long long aw = pk2(a.w, a.w);
                ffma2(acc[0][0], ax, w01); ffma2(acc[0][1], ax, w23);
                ffma2(acc[1][0], ay, w01); ffma2(acc[1][1], ay, w23);
                ffma2(acc[2][0], az, w01); ffma2(acc[2][1], az, w23);
                ffma2(acc[3][0], aw, w01); ffma2(acc[3][1], aw, w23);
            }
        }

        int m0 = q * 4;
        #pragma unroll
        for (int i = 0; i < 4; i++) {
            int n = n0 + m0 + i;
            if (n < NN) {
                float o0, o1, o2, o3;
                upk2(o0, o1, acc[i][0]);
                upk2(o2, o3, acc[i][1]);
                float4 o = make_float4(fmaxf(o0, 0.f), fmaxf(o1, 0.f),
                                       fmaxf(o2, 0.f), fmaxf(o3, 0.f));
                *(float4*)&out[(size_t)n * DD + d0] = o;
            }
        }
        __syncthreads();
    }
}

// ---------- global mean pool ----------
__global__ void k_pool(const float* __restrict__ h, const int* __restrict__ batch,
                       float* __restrict__ pool, float* __restrict__ gcnt) {
    int t = blockIdx.x * blockDim.x + threadIdx.x;
    if (t >= NN * 4) return;
    int n = t >> 2, j = t & 3;
    int g = batch[n];
    const float4* hr = (const float4*)(h + (size_t)n * DD) + j * 4;
    float* p = pool + (size_t)g * DD + (size_t)j * 16;
    #pragma unroll
    for (int i = 0; i < 4; i++) red_v4(p + i * 4, hr[i]);
    if (j == 0) atomicAdd(&gcnt[g], 1.0f);
}

// ---------- classifier ----------
__global__ void k_out(const float* __restrict__ pool, const float* __restrict__ gcnt,
                      const float* __restrict__ Wout, const float* __restrict__ bout,
                      float* __restrict__ out) {
    int t = blockIdx.x * blockDim.x + threadIdx.x;
    if (t >= NG * 2) return;
    int g = t >> 1, c = t & 1;
    float inv = 1.0f / fmaxf(gcnt[g], 1.0f);
    float acc = bout[c];
    const float* p = pool + (size_t)g * DD;
    const float* w = Wout + (size_t)c * DD;
    #pragma unroll
    for (int k = 0; k < DD; k++) acc += p[k] * inv * w[k];
    out[(size_t)g * 2 + c] = acc;
}

extern "C" void kernel_launch(void* const* d_in, const int* in_sizes, int n_in,
                              void* d_out, int out_size) {
    const int*   x     = (const int*)d_in[0];
    const int*   ei    = (const int*)d_in[1];
    const int*   src   = ei;          // edge_index[0]
    const int*   dst   = ei + NE;     // edge_index[1]
    const int*   batch = (const int*)d_in[2];
    const float* emb   = (const float*)d_in[3];
    const float* W1l   = (const float*)d_in[4];
    const float* b1l   = (const float*)d_in[5];
    const float* W1r   = (const float*)d_in[6];
    const float* W2l   = (const float*)d_in[7];
    const float* b2l   = (const float*)d_in[8];
    const float* W2r   = (const float*)d_in[9];
    const float* Wout  = (const float*)d_in[10];
    const float* bout  = (const float*)d_in[11];
    float* out = (float*)d_out;

    float *h0, *h1, *h2, *mean, *pool, *gcnt;
    int *deg, *off, *cursor, *elist, *bsum, *bpre;
    cudaGetSymbolAddress((void**)&h0,     g_h0);
    cudaGetSymbolAddress((void**)&h1,     g_h1);
    cudaGetSymbolAddress((void**)&h2,     g_h2);
    cudaGetSymbolAddress((void**)&mean,   g_agg);
    cudaGetSymbolAddress((void**)&pool,   g_pool);
    cudaGetSymbolAddress((void**)&gcnt,   g_gcnt);
    cudaGetSymbolAddress((void**)&deg,    g_deg);
    cudaGetSymbolAddress((void**)&off,    g_off);
    cudaGetSymbolAddress((void**)&cursor, g_cursor);
    cudaGetSymbolAddress((void**)&elist,  g_elist);
    cudaGetSymbolAddress((void**)&bsum,   g_bsum);
    cudaGetSymbolAddress((void**)&bpre,   g_bpre);

    const int SMEM_LIN = (128 * 64 + 128 * SA_STRIDE) * 4;   // 67584 bytes
    cudaFuncSetAttribute(k_linear, cudaFuncAttributeMaxDynamicSharedMemorySize, SMEM_LIN);

    cudaMemsetAsync(deg,    0, NN * sizeof(int));
    cudaMemsetAsync(cursor, 0, NN * sizeof(int));
    cudaMemsetAsync(pool,   0, (size_t)NG * DD * sizeof(float));
    cudaMemsetAsync(gcnt,   0, NG * sizeof(float));

    const int T = 256;
    // Embedding + CSR build (CSR reused by both layers)
    k_gather<<<(NN * 16 + T - 1) / T, T>>>(x, emb, h0);
    k_deg<<<(NE + T - 1) / T, T>>>(dst, deg);
    k_scan_part<<<SCAN_NB, SCAN_B>>>(deg, bsum);
    k_scan_mid<<<1, 128>>>(bsum, bpre);
    k_scan_add<<<SCAN_NB, SCAN_B>>>(deg, bpre, off);
    k_fill<<<(NE + T - 1) / T, T>>>(src, dst, off, cursor, elist);

    // Layer 1
    k_aggmean<<<(NN * 32 + T - 1) / T, T>>>(h0, elist, off, deg, mean);
    k_linear<<<444, 256, SMEM_LIN>>>(mean, h0, W1l, b1l, W1r, h1);

    // Layer 2
    k_aggmean<<<(NN * 32 + T - 1) / T, T>>>(h1, elist, off, deg, mean);
    k_linear<<<444, 256, SMEM_LIN>>>(mean, h1, W2l, b2l, W2r, h2);

    // Pool + classify
    k_pool<<<(NN * 4 + T - 1) / T, T>>>(h2, batch, pool, gcnt);
    k_out<<<(NG * 2 + 127) / 128, 128>>>(pool, gcnt, Wout, bout, out);
}